// round 17
// baseline (speedup 1.0000x reference)
#include <cuda_runtime.h>
#include <cuda_bf16.h>
#include <math.h>

// Problem constants
#define BB 32
#define SS 512
#define II 512
#define HH 1024
#define OO 512
#define G4 4096          // 4*H
#define LDW 1536         // I+H, row stride of the gate weight matrices
#define NB 128           // persistent scan blocks (1 per SM, <= 148)

// packed fp32x2 FMA
#define FMA2(acc, a, b) \
    asm("fma.rn.f32x2 %0, %1, %2, %0;" : "+l"(acc) : "l"(a), "l"(b))

__device__ __forceinline__ float2 unpack2(unsigned long long v) {
    float2 r;
    asm("mov.b64 {%0, %1}, %2;" : "=f"(r.x), "=f"(r.y) : "l"(v));
    return r;
}
__device__ __forceinline__ unsigned long long dup2(float x) {
    unsigned long long r;
    asm("mov.b64 %0, {%1, %1};" : "=l"(r) : "f"(x));
    return r;
}

// -------------------- scratch (device globals; no allocations) --------------------
__device__ float g_xg[(size_t)SS * BB * G4];   // [b][s][4H] row m = b*S+s   (256 MB)
__device__ float g_hs[(size_t)BB * SS * HH];   // [b][s][H]  row m = b*S+s   (64 MB)
__device__ float g_htA[BB * HH];               // h quad-major: [H/4][B] float4
__device__ float g_htB[BB * HH];
__device__ float g_c [BB * HH];                // c transposed: [u][b]
__device__ unsigned g_bar;                     // CG-style barrier counter

// -------------------- utility kernels --------------------
__global__ void scan_init(float* __restrict__ hA, unsigned* __restrict__ bar) {
    int i = blockIdx.x * blockDim.x + threadIdx.x;
    if (i < BB * HH) hA[i] = 0.0f;
    if (i == 0) *bar = 0u;
}

// final h quad-major [u>>2][b][u&3], c in [u][b]; emit [b][H] for both
__global__ void copy_finals(const float* __restrict__ ht, const float* __restrict__ c,
                            float* __restrict__ out) {
    int i = blockIdx.x * blockDim.x + threadIdx.x;   // i = b*HH + u
    if (i < BB * HH) {
        int b = i >> 10, u = i & (HH - 1);
        out[i]           = ht[((u >> 2) * 32 + b) * 4 + (u & 3)];
        out[BB * HH + i] = c[u * BB + b];
    }
}

// -------------------- SGEMM: C[M,N] = A[M,K] @ Bw[N,K]^T + bias[N] --------------------
// BM=BN=128, BK=16, 256 threads, 8x8 per thread. (~42 TF/s, near fp32 SIMT peak.)
__global__ __launch_bounds__(256, 2)
void sgemm_tn(int M, int N, int K,
              const float* __restrict__ A, int lda,
              const float* __restrict__ Bw, int ldb,
              const float* __restrict__ bias,
              float* __restrict__ C, int ldc) {
    __shared__ float As[16][128];
    __shared__ float Bs[16][128];

    const int tid = threadIdx.x;
    const int rowBase = blockIdx.y * 128;
    const int colBase = blockIdx.x * 128;

    const int ldRow = tid >> 2;
    const int ldK   = (tid & 3) << 2;

    const int tx = tid & 15;
    const int ty = tid >> 4;

    unsigned long long acc[8][4];
#pragma unroll
    for (int i = 0; i < 8; i++)
#pragma unroll
        for (int j = 0; j < 4; j++) acc[i][j] = 0ull;

    for (int k0 = 0; k0 < K; k0 += 16) {
#pragma unroll
        for (int r = 0; r < 128; r += 64) {
            float4 va = *reinterpret_cast<const float4*>(
                A + (size_t)(rowBase + ldRow + r) * lda + k0 + ldK);
            As[ldK + 0][ldRow + r] = va.x;
            As[ldK + 1][ldRow + r] = va.y;
            As[ldK + 2][ldRow + r] = va.z;
            As[ldK + 3][ldRow + r] = va.w;
        }
#pragma unroll
        for (int r = 0; r < 128; r += 64) {
            float4 vb = *reinterpret_cast<const float4*>(
                Bw + (size_t)(colBase + ldRow + r) * ldb + k0 + ldK);
            Bs[ldK + 0][ldRow + r] = vb.x;
            Bs[ldK + 1][ldRow + r] = vb.y;
            Bs[ldK + 2][ldRow + r] = vb.z;
            Bs[ldK + 3][ldRow + r] = vb.w;
        }
        __syncthreads();

#pragma unroll
        for (int kk = 0; kk < 16; kk++) {
            float ar[8];
#pragma unroll
            for (int i = 0; i < 8; i++) ar[i] = As[kk][ty * 8 + i];
            const ulonglong2* bp =
                reinterpret_cast<const ulonglong2*>(&Bs[kk][tx * 8]);
            ulonglong2 b01 = bp[0];
            ulonglong2 b23 = bp[1];
#pragma unroll
            for (int i = 0; i < 8; i++) {
                unsigned long long a2 = dup2(ar[i]);
                FMA2(acc[i][0], a2, b01.x);
                FMA2(acc[i][1], a2, b01.y);
                FMA2(acc[i][2], a2, b23.x);
                FMA2(acc[i][3], a2, b23.y);
            }
        }
        __syncthreads();
    }

#pragma unroll
    for (int i = 0; i < 8; i++) {
        float* crow = C + (size_t)(rowBase + ty * 8 + i) * ldc + colBase + tx * 8;
#pragma unroll
        for (int j = 0; j < 2; j++) {
            float2 p0 = unpack2(acc[i][2 * j + 0]);
            float2 p1 = unpack2(acc[i][2 * j + 1]);
            float4 v;
            v.x = p0.x + bias[colBase + tx * 8 + 4 * j + 0];
            v.y = p0.y + bias[colBase + tx * 8 + 4 * j + 1];
            v.z = p1.x + bias[colBase + tx * 8 + 4 * j + 2];
            v.w = p1.y + bias[colBase + tx * 8 + 4 * j + 3];
            *reinterpret_cast<float4*>(crow + 4 * j) = v;
        }
    }
}

// -------------------- grid-wide barrier (cooperative-groups sync_grids pattern) ----
__device__ __forceinline__ void grid_sync(unsigned* bar) {
    __syncthreads();
    if (threadIdx.x == 0) {
        __threadfence();
        unsigned add = (blockIdx.x == 0) ? (0x80000000u - (NB - 1)) : 1u;
        unsigned old = atomicAdd(bar, add);
        while (((old ^ *(volatile unsigned*)bar) & 0x80000000u) == 0u) { }
        __threadfence();
    }
    __syncthreads();
}

// -------------------- persistent recurrent scan --------------------
// 128 blocks x 512 threads (16 warps), one block per SM, all 512 steps in one
// launch. Block bk owns gate-rows u in [bk*8, bk*8+8). SPLIT-K: warp (w, half)
// handles u = bk*8+w over k in [half*512, half*512+512); lane = batch.
// 4 warps/SMSP -> h-ring L2 latency hidden by warp interleave (R12 had 2/SMSP).
// Weights (128 KB) resident in smem (R12 layout); h double-buffered in global
// quad-major ht[k4][b] (float4); 8-deep LDG ring. Cross-half reduction via a
// 4 KB smem scratch. c lives in half=0 warp registers for all 512 steps.
#define SCAN_SMEM (131072 + 4096)

#define SCAN_FMA8()                                              \
    do {                                                          \
        FMA2(aF0, A0.x, hv.x); FMA2(aI0, A0.y, hv.x);             \
        FMA2(aO0, A1.x, hv.x); FMA2(aC0, A1.y, hv.x);             \
        FMA2(aF1, B0.x, hv.y); FMA2(aI1, B0.y, hv.y);             \
        FMA2(aO1, B1.x, hv.y); FMA2(aC1, B1.y, hv.y);             \
    } while (0)

__global__ __launch_bounds__(512, 1)
void lstm_scan(const float* __restrict__ xg,
               float* bufA, float* bufB,
               float* __restrict__ cfin, float* __restrict__ hs,
               unsigned* bar,
               const float* __restrict__ Wf, const float* __restrict__ Wi,
               const float* __restrict__ Wo, const float* __restrict__ Wc) {
    extern __shared__ float wsm[];   // [0,32768): weights; [32768,+1024): reduction
    const int tid  = threadIdx.x;
    const int bk   = blockIdx.x;
    const int b    = tid & 31;       // lane = batch
    const int wid  = tid >> 5;       // 0..15
    const int w    = wid & 7;        // u-row within block
    const int half = wid >> 3;       // k-split half
    const int u    = bk * 8 + w;     // global gate-row

    // one-time: weights -> smem (same layout as R12)
    for (int i = tid; i < 4 * 8 * 1024; i += 512) {
        int g  = i >> 13;            // gate
        int ww = (i >> 10) & 7;      // warp-row
        int k  = i & 1023;
        const float* Wsrc = (g == 0) ? Wf : (g == 1) ? Wi : (g == 2) ? Wo : Wc;
        wsm[(((ww * 512 + (k >> 1)) * 4 + g) << 1) + (k & 1)] =
            Wsrc[(size_t)(bk * 8 + ww) * LDW + II + k];
    }
    __syncthreads();

    const ulonglong2* wqw = reinterpret_cast<const ulonglong2*>(wsm)
                          + (size_t)w * 1024 + (size_t)half * 512;
    float4* red4 = reinterpret_cast<float4*>(wsm + 32768);   // [8][32]

    float creg = 0.0f;
    float* cur = bufA;
    float* nxt = bufB;

    for (int s = 0; s < SS; s++) {
        // xg tail values (half=0 warps consume them at the end; issue early)
        const float* xr = xg + ((size_t)b * SS + s) * G4;
        float xf = 0.f, xi = 0.f, xo = 0.f, xc = 0.f;
        if (half == 0) {
            xf = xr[u];
            xi = xr[HH + u];
            xo = xr[2 * HH + u];
            xc = xr[3 * HH + u];
        }

        unsigned long long aF0 = 0ull, aF1 = 0ull, aI0 = 0ull, aI1 = 0ull;
        unsigned long long aO0 = 0ull, aO1 = 0ull, aC0 = 0ull, aC1 = 0ull;

        // this warp's half of h: k4 in [half*128, half*128+128)
        const ulonglong2* hqw = reinterpret_cast<const ulonglong2*>(cur)
                              + b + (size_t)half * 128 * 32;

        // 8-deep h prefetch ring
        ulonglong2 ring[8];
#pragma unroll
        for (int j = 0; j < 8; j++) ring[j] = hqw[j * 32];

#pragma unroll 8
        for (int t = 0; t < 120; t++) {
            ulonglong2 hv = ring[t & 7];
            ring[t & 7] = hqw[(t + 8) * 32];
            ulonglong2 A0 = wqw[t * 4 + 0];
            ulonglong2 A1 = wqw[t * 4 + 1];
            ulonglong2 B0 = wqw[t * 4 + 2];
            ulonglong2 B1 = wqw[t * 4 + 3];
            SCAN_FMA8();
        }
#pragma unroll
        for (int t = 120; t < 128; t++) {
            ulonglong2 hv = ring[t & 7];
            ulonglong2 A0 = wqw[t * 4 + 0];
            ulonglong2 A1 = wqw[t * 4 + 1];
            ulonglong2 B0 = wqw[t * 4 + 2];
            ulonglong2 B1 = wqw[t * 4 + 3];
            SCAN_FMA8();
        }

        float2 t2;
        t2 = unpack2(aF0); float gf = t2.x + t2.y;
        t2 = unpack2(aF1); gf += t2.x + t2.y;
        t2 = unpack2(aI0); float gi = t2.x + t2.y;
        t2 = unpack2(aI1); gi += t2.x + t2.y;
        t2 = unpack2(aO0); float go = t2.x + t2.y;
        t2 = unpack2(aO1); go += t2.x + t2.y;
        t2 = unpack2(aC0); float gc = t2.x + t2.y;
        t2 = unpack2(aC1); gc += t2.x + t2.y;

        // cross-half reduction via smem
        if (half == 1) red4[w * 32 + b] = make_float4(gf, gi, go, gc);
        __syncthreads();

        if (half == 0) {
            float4 r = red4[w * 32 + b];
            gf += r.x + xf;
            gi += r.y + xi;
            go += r.z + xo;
            gc += r.w + xc;

            float f  = 1.0f / (1.0f + expf(-gf));
            float ig = 1.0f / (1.0f + expf(-gi));
            float og = 1.0f / (1.0f + expf(-go));

            float cn = f * creg + ig * tanhf(gc);
            creg = cn;
            float hn = og * tanhf(cn);

            nxt[((u >> 2) * 32 + b) * 4 + (u & 3)] = hn;
            hs[((size_t)b * SS + s) * HH + u] = hn;
        }

        grid_sync(bar);

        float* tmp = cur; cur = nxt; nxt = tmp;
    }
    // after 512 steps (even count) final h sits in bufA; write final c
    if (half == 0) cfin[u * BB + b] = creg;
}

// -------------------- launch --------------------
extern "C" void kernel_launch(void* const* d_in, const int* in_sizes, int n_in,
                              void* d_out, int out_size) {
    (void)in_sizes; (void)n_in;
    const float* x    = (const float*)d_in[0];
    const float* Wf_w = (const float*)d_in[1];
    const float* Wf_b = (const float*)d_in[2];
    const float* Wi_w = (const float*)d_in[3];
    const float* Wi_b = (const float*)d_in[4];
    const float* Wo_w = (const float*)d_in[5];
    const float* Wo_b = (const float*)d_in[6];
    const float* Wc_w = (const float*)d_in[7];
    const float* Wc_b = (const float*)d_in[8];
    const float* out_w = (const float*)d_in[9];
    const float* out_b = (const float*)d_in[10];

    float *xg, *hs, *hA, *hB, *c;
    unsigned* bar;
    cudaGetSymbolAddress((void**)&xg, g_xg);
    cudaGetSymbolAddress((void**)&hs, g_hs);
    cudaGetSymbolAddress((void**)&hA, g_htA);
    cudaGetSymbolAddress((void**)&hB, g_htB);
    cudaGetSymbolAddress((void**)&c,  g_c);
    cudaGetSymbolAddress((void**)&bar, g_bar);

    cudaFuncSetAttribute(lstm_scan, cudaFuncAttributeMaxDynamicSharedMemorySize, SCAN_SMEM);

    // reset h0 and barrier counter (deterministic across graph replays)
    scan_init<<<128, 256>>>(hA, bar);

    const int M = BB * SS;  // 16384, row m = b*S+s

    // phase 1: xg[m][g] = x @ Wx^T + b   (4 gate GEMMs: N=1024, K=512)
    {
        dim3 grid(HH / 128, M / 128);
        sgemm_tn<<<grid, 256>>>(M, HH, II, x, II, Wf_w, LDW, Wf_b, xg + 0 * HH, G4);
        sgemm_tn<<<grid, 256>>>(M, HH, II, x, II, Wi_w, LDW, Wi_b, xg + 1 * HH, G4);
        sgemm_tn<<<grid, 256>>>(M, HH, II, x, II, Wo_w, LDW, Wo_b, xg + 2 * HH, G4);
        sgemm_tn<<<grid, 256>>>(M, HH, II, x, II, Wc_w, LDW, Wc_b, xg + 3 * HH, G4);
    }

    // phase 2: ONE persistent launch for all 512 steps (512 threads: split-k)
    lstm_scan<<<NB, 512, SCAN_SMEM>>>(xg, hA, hB, c, hs, bar,
                                      Wf_w, Wi_w, Wo_w, Wc_w);

    // phase 3: final = hs @ out_w^T + out_b  (M=16384, N=512, K=1024)
    {
        dim3 grid(OO / 128, M / 128);
        sgemm_tn<<<grid, 256>>>(M, OO, HH, hs, HH, out_w, HH, out_b, (float*)d_out, OO);
    }

    // tail outputs (h_fin, c_fin) if the flattened output includes them
    long long need = (long long)BB * SS * OO + 2LL * BB * HH;
    if ((long long)out_size >= need) {
        copy_finals<<<128, 256>>>(hA, c, (float*)d_out + (size_t)BB * SS * OO);
    }
}